// round 1
// baseline (speedup 1.0000x reference)
#include <cuda_runtime.h>
#include <math.h>

#define Bn 8
#define Hh 640
#define Ww 640
#define HW (Hh*Ww)          // 409600
#define NCH 10
#define NKER 5
#define NL 16
#define NEGINF (-1e30f)

// ---------------- scratch (device globals; no allocation allowed) ----------
__device__ float    g_prob[Bn*HW];
__device__ float    g_tmp [Bn*HW];
__device__ float    g_dil [Bn*HW];
__device__ unsigned g_negbits[Bn*HW];
__device__ int      g_negcount[Bn];
__device__ int      g_npos[Bn];
__device__ float    g_posSum[Bn], g_posSum2[Bn];
__device__ unsigned g_hist[Bn][4096];
__device__ unsigned g_prefix[Bn];
__device__ int      g_kRem[Bn];
__device__ int      g_k[Bn];
__device__ float    g_negselSum[Bn];
__device__ float    g_kInter[Bn*NKER], g_kU1[Bn*NKER], g_kU2[Bn*NKER];
__device__ float    g_embCnt[Bn][NL];
__device__ float    g_embSum[Bn][NL][4];
__device__ float    g_embCv[Bn][NL];
__device__ float    g_mean[Bn][NL][4];

// ---------------- helpers ----------------
__device__ __forceinline__ float sigm(float x){ return 1.0f/(1.0f+expf(-x)); }

__device__ float blkSum(float v){
    __shared__ float sh[32];
    int lane = threadIdx.x & 31, wid = threadIdx.x >> 5;
    __syncthreads();                       // safe reuse across calls
    #pragma unroll
    for (int o=16;o;o>>=1) v += __shfl_down_sync(0xffffffffu, v, o);
    if (lane==0) sh[wid]=v;
    __syncthreads();
    int nw = blockDim.x >> 5;
    v = (threadIdx.x < nw) ? sh[threadIdx.x] : 0.f;
    if (wid==0){
        #pragma unroll
        for (int o=16;o;o>>=1) v += __shfl_down_sync(0xffffffffu, v, o);
    }
    return v;   // valid on thread 0
}

// ---------------- kernels ----------------
__global__ void k_zero(){
    int idx = blockIdx.x*blockDim.x + threadIdx.x;
    if (idx < Bn*4096) ((unsigned*)g_hist)[idx] = 0u;
    if (idx < Bn){
        g_negcount[idx]=0; g_npos[idx]=0; g_posSum[idx]=0.f; g_posSum2[idx]=0.f;
        g_negselSum[idx]=0.f; g_prefix[idx]=0u; g_kRem[idx]=0; g_k[idx]=0;
    }
    if (idx < Bn*NKER){ g_kInter[idx]=0.f; g_kU1[idx]=0.f; g_kU2[idx]=0.f; }
    if (idx < Bn*NL){ ((float*)g_embCnt)[idx]=0.f; ((float*)g_embCv)[idx]=0.f; }
    if (idx < Bn*NL*4) ((float*)g_embSum)[idx]=0.f;
}

__global__ void k_sigmoid(const float* __restrict__ pred){
    int idx = blockIdx.x*blockDim.x + threadIdx.x;
    if (idx >= Bn*HW) return;
    int b = idx / HW;
    int i = idx - b*HW;
    g_prob[idx] = sigm(pred[b*NCH*HW + i]);
}

__global__ void k_hmax(){
    int idx = blockIdx.x*blockDim.x + threadIdx.x;
    if (idx >= Bn*HW) return;
    int b = idx / HW;
    int i = idx - b*HW;
    int y = i / Ww, x = i - y*Ww;
    const float* row = g_prob + b*HW + y*Ww;
    float m = NEGINF;
    #pragma unroll
    for (int dx=-4; dx<=4; dx++){
        int xx = x+dx;
        if (xx>=0 && xx<Ww) m = fmaxf(m, row[xx]);
    }
    g_tmp[idx] = m;
}

#define SEGS 10
#define SEGLEN 64
__global__ void k_vmax(){
    int t = blockIdx.x*blockDim.x + threadIdx.x;
    if (t >= Bn*Ww*SEGS) return;
    int b   = t / (Ww*SEGS);
    int r   = t - b*(Ww*SEGS);
    int seg = r / Ww;
    int x   = r - seg*Ww;
    int base = b*HW + x;
    int y0 = seg*SEGLEN;
    float buf[9];
    #pragma unroll
    for (int j=0;j<9;j++){
        int row = y0-4+j;
        buf[j] = (row>=0 && row<Hh) ? g_tmp[base+row*Ww] : NEGINF;
    }
    for (int yo=0; yo<SEGLEN; yo++){
        float m = fmaxf(fmaxf(fmaxf(buf[0],buf[1]),fmaxf(buf[2],buf[3])),
                        fmaxf(fmaxf(buf[4],buf[5]),fmaxf(fmaxf(buf[6],buf[7]),buf[8])));
        g_dil[base + (y0+yo)*Ww] = m;
        #pragma unroll
        for (int j=0;j<8;j++) buf[j]=buf[j+1];
        int nr = y0+yo+5;
        buf[8] = (nr<Hh) ? g_tmp[base+nr*Ww] : NEGINF;
    }
}

// stats + compaction of negative score bits   grid: (40, Bn) x 256  (stride 10240 divides HW)
__global__ void k_textstats(const float* __restrict__ gtText,
                            const float* __restrict__ tm){
    int b = blockIdx.y;
    int stride = gridDim.x*blockDim.x;
    int pc = 0; float ps = 0.f, ps2 = 0.f;
    for (int i = blockIdx.x*blockDim.x + threadIdx.x; i < HW; i += stride){
        float v  = g_dil[b*HW+i];
        float gt = gtText[b*HW+i];
        float m  = tm[b*HW+i];
        bool isPos = (gt > 0.5f) && (m > 0.5f);
        bool isNeg = (gt <= 0.5f) && (m > 0.5f);
        if (isPos){ pc++; ps += v; ps2 += v*v; }
        unsigned ball = __ballot_sync(0xffffffffu, isNeg);
        if (isNeg){
            int lane = threadIdx.x & 31;
            int rank = __popc(ball & ((1u<<lane)-1u));
            int leader = __ffs(ball)-1;
            int base = 0;
            if (lane == leader) base = atomicAdd(&g_negcount[b], __popc(ball));
            base = __shfl_sync(ball, base, leader);
            g_negbits[b*HW + base + rank] = __float_as_uint(v);
        }
    }
    float tpc = blkSum((float)pc);
    float tps = blkSum(ps);
    float tps2 = blkSum(ps2);
    if (threadIdx.x==0){
        atomicAdd(&g_npos[b], (int)tpc);
        atomicAdd(&g_posSum[b], tps);
        atomicAdd(&g_posSum2[b], tps2);
    }
}

// level histograms over compacted bits  grid: (20, Bn) x 256
__global__ void k_hist(int level){
    __shared__ unsigned h[4096];
    int b = blockIdx.y;
    for (int t = threadIdx.x; t < 4096; t += blockDim.x) h[t]=0u;
    __syncthreads();
    int cnt = g_negcount[b];
    unsigned prefix = g_prefix[b];
    int stride = gridDim.x*blockDim.x;
    const unsigned* nb = g_negbits + b*HW;
    for (int j = blockIdx.x*blockDim.x + threadIdx.x; j < cnt; j += stride){
        unsigned bits = nb[j];
        if (level==1){
            atomicAdd(&h[bits>>20], 1u);
        } else if (level==2){
            if ((bits>>20) == (prefix>>20)) atomicAdd(&h[(bits>>8)&0xFFFu], 1u);
        } else {
            if ((bits>>8) == (prefix>>8)) atomicAdd(&h[bits & 0xFFu], 1u);
        }
    }
    __syncthreads();
    for (int t = threadIdx.x; t < 4096; t += blockDim.x)
        if (h[t]) atomicAdd(&g_hist[b][t], h[t]);
}

// select bin at this level, update prefix/kRem, then clear this batch's hist   grid: Bn x 256
__global__ void k_select(int level, int nbins){
    int b = blockIdx.x;
    if (threadIdx.x==0){
        int k;
        if (level==1){
            k = 3*g_npos[b];
            int nt = g_negcount[b];
            if (k > nt) k = nt;
            g_k[b] = k;
        } else {
            k = g_kRem[b];
        }
        long long acc = 0;
        int chosen = 0;
        for (int bin = nbins-1; bin >= 0; bin--){
            unsigned c = g_hist[b][bin];
            if (acc + (long long)c >= (long long)k){ chosen = bin; break; }
            acc += c;
        }
        g_kRem[b] = k - (int)acc;
        if (level==1)      g_prefix[b] = ((unsigned)chosen) << 20;
        else if (level==2) g_prefix[b] |= ((unsigned)chosen) << 8;
        else               g_prefix[b] |= (unsigned)chosen;
    }
    __syncthreads();
    for (int t = threadIdx.x; t < 4096; t += blockDim.x) g_hist[b][t] = 0u;
}

// sum dil^2 over negatives strictly above threshold   grid: (20, Bn) x 256
__global__ void k_negsum(){
    int b = blockIdx.y;
    unsigned T = g_prefix[b];
    int cnt = g_negcount[b];
    int stride = gridDim.x*blockDim.x;
    const unsigned* nb = g_negbits + b*HW;
    float s = 0.f;
    for (int j = blockIdx.x*blockDim.x + threadIdx.x; j < cnt; j += stride){
        unsigned bits = nb[j];
        if (bits > T){ float v = __uint_as_float(bits); s += v*v; }
    }
    float ts = blkSum(s);
    if (threadIdx.x==0) atomicAdd(&g_negselSum[b], ts);
}

// kernels dice sums   grid: (20, 40) x 256
__global__ void k_kern(const float* __restrict__ pred,
                       const float* __restrict__ gtk,
                       const float* __restrict__ tm){
    int row = blockIdx.y;            // 0..39
    int b  = row / NKER;
    int kc = row - b*NKER;
    const float* pp = pred + (b*NCH + 1 + kc)*HW;
    const float* gg = gtk  + (b*NKER + kc)*HW;
    const float* mm = tm   + b*HW;
    int stride = gridDim.x*blockDim.x;
    float si=0.f, s1=0.f, s2=0.f;
    for (int i = blockIdx.x*blockDim.x + threadIdx.x; i < HW; i += stride){
        float m = mm[i];
        if (m > 0.5f){
            float p = sigm(pp[i]);
            float g = gg[i];
            si += p*g;
            s1 += p*p;
            s2 += g;
        }
    }
    float ti = blkSum(si);
    float t1 = blkSum(s1);
    float t2 = blkSum(s2);
    if (threadIdx.x==0){
        atomicAdd(&g_kInter[row], ti);
        atomicAdd(&g_kU1[row], t1);
        atomicAdd(&g_kU2[row], t2);
    }
}

// emb pass 1: per-label counts + sums   grid: (40, Bn) x 256
__global__ void k_emb1(const float* __restrict__ pred,
                       const int* __restrict__ inst,
                       const float* __restrict__ tm){
    __shared__ float sC[NL];
    __shared__ float sS[NL][4];
    int b = blockIdx.y;
    if (threadIdx.x < NL){ sC[threadIdx.x]=0.f;
        for (int d=0;d<4;d++) sS[threadIdx.x][d]=0.f; }
    __syncthreads();
    int stride = gridDim.x*blockDim.x;
    const float* e0 = pred + (b*NCH + 6)*HW;
    for (int i = blockIdx.x*blockDim.x + threadIdx.x; i < HW; i += stride){
        float m = tm[b*HW+i];
        if (m > 0.5f){
            int g = inst[b*HW+i] & 15;
            atomicAdd(&sC[g], 1.f);
            #pragma unroll
            for (int d=0;d<4;d++) atomicAdd(&sS[g][d], e0[d*HW + i]);
        }
    }
    __syncthreads();
    if (threadIdx.x < NL){
        int l = threadIdx.x;
        if (sC[l] != 0.f) atomicAdd(&g_embCnt[b][l], sC[l]);
        for (int d=0;d<4;d++)
            if (sS[l][d] != 0.f) atomicAdd(&g_embSum[b][l][d], sS[l][d]);
    }
}

__global__ void k_means(){
    int t = blockIdx.x*blockDim.x + threadIdx.x;
    if (t >= Bn*NL) return;
    int b = t / NL, l = t - b*NL;
    float c = g_embCnt[b][l];
    float inv = 1.f / fmaxf(c, 1.f);
    #pragma unroll
    for (int d=0;d<4;d++) g_mean[b][l][d] = g_embSum[b][l][d]*inv;
}

// emb pass 2: hinge variance   grid: (40, Bn) x 256
__global__ void k_emb2(const float* __restrict__ pred,
                       const int* __restrict__ inst,
                       const float* __restrict__ tm){
    __shared__ float sCv[NL];
    __shared__ float sM[NL][4];
    int b = blockIdx.y;
    if (threadIdx.x < NL){ sCv[threadIdx.x]=0.f;
        for (int d=0;d<4;d++) sM[threadIdx.x][d]=g_mean[b][threadIdx.x][d]; }
    __syncthreads();
    int stride = gridDim.x*blockDim.x;
    const float* e0 = pred + (b*NCH + 6)*HW;
    for (int i = blockIdx.x*blockDim.x + threadIdx.x; i < HW; i += stride){
        float m = tm[b*HW+i];
        if (m > 0.5f){
            int g = inst[b*HW+i] & 15;
            float d2 = 0.f;
            #pragma unroll
            for (int d=0;d<4;d++){
                float df = e0[d*HW + i] - sM[g][d];
                d2 += df*df;
            }
            float dd = sqrtf(d2 + 1e-12f);
            float h = dd - 0.5f;
            if (h > 0.f) atomicAdd(&sCv[g], h*h);
        }
    }
    __syncthreads();
    if (threadIdx.x < NL && sCv[threadIdx.x] != 0.f)
        atomicAdd(&g_embCv[b][threadIdx.x], sCv[threadIdx.x]);
}

__global__ void k_final(float* out){
    if (threadIdx.x != 0 || blockIdx.x != 0) return;
    // loss_text
    float loss_text = 0.f;
    for (int b=0;b<Bn;b++){
        float inter = g_posSum[b];
        float uni = g_posSum2[b] + g_negselSum[b] + (float)g_npos[b] + 1e-6f;
        if (g_kRem[b] > 0){
            float tv = __uint_as_float(g_prefix[b]);
            uni += (float)g_kRem[b]*tv*tv;
        }
        loss_text += 1.f - 2.f*inter/uni;
    }
    loss_text /= (float)Bn;
    // loss_kernels
    float loss_k = 0.f;
    for (int r=0;r<Bn*NKER;r++){
        float uni = g_kU1[r] + g_kU2[r] + 1e-6f;
        loss_k += 1.f - 2.f*g_kInter[r]/uni;
    }
    loss_k /= (float)(Bn*NKER);
    // loss_emb
    float lvT=0.f, ldT=0.f, lrT=0.f;
    for (int b=0;b<Bn;b++){
        int n=0;
        bool pres[NL];
        for (int l=0;l<NL;l++){ pres[l] = g_embCnt[b][l] > 0.f; if (pres[l]) n++; }
        float nf = (float)n;
        float lv = 0.f;
        for (int l=0;l<NL;l++)
            if (pres[l]) lv += g_embCv[b][l] / fmaxf(g_embCnt[b][l], 1.f);
        lv /= fmaxf(nf, 1.f);
        float ld = 0.f;
        for (int i=0;i<NL;i++) for (int j=i+1;j<NL;j++){
            if (pres[i] && pres[j]){
                float d2=0.f;
                for (int d=0;d<4;d++){
                    float df = g_mean[b][i][d]-g_mean[b][j][d];
                    d2 += df*df;
                }
                float pd = sqrtf(d2 + 1e-12f);
                float h = fmaxf(3.0f - pd, 0.f);
                ld += h*h;
            }
        }
        ld /= fmaxf(nf*(nf-1.f), 1.f);
        float lr = 0.f;
        for (int l=0;l<NL;l++){
            if (pres[l]){
                float d2=0.f;
                for (int d=0;d<4;d++) d2 += g_mean[b][l][d]*g_mean[b][l][d];
                lr += sqrtf(d2 + 1e-12f);
            }
        }
        lr /= fmaxf(nf, 1.f);
        float act = (n > 1) ? 1.f : 0.f;
        lvT += act*lv; ldT += act*ld; lrT += act*lr;
    }
    float loss_emb = 0.25f*(lvT + ldT + 0.001f*(lrT/(float)Bn));
    float loss = loss_k + 0.5f*loss_text + loss_emb;
    out[0]=loss; out[1]=loss_text; out[2]=loss_k; out[3]=loss_emb;
}

// ---------------- launch ----------------
extern "C" void kernel_launch(void* const* d_in, const int* in_sizes, int n_in,
                              void* d_out, int out_size){
    const float* pred   = (const float*)d_in[0];
    const float* gtText = (const float*)d_in[1];
    const float* gtk    = (const float*)d_in[2];
    const float* tm     = (const float*)d_in[3];
    const int*   inst   = (const int*)d_in[4];
    float* out = (float*)d_out;

    k_zero<<<(Bn*4096+255)/256, 256>>>();
    k_sigmoid<<<(Bn*HW+255)/256, 256>>>(pred);
    k_hmax<<<(Bn*HW+255)/256, 256>>>();
    k_vmax<<<(Bn*Ww*SEGS+255)/256, 256>>>();
    k_textstats<<<dim3(40, Bn), 256>>>(gtText, tm);
    k_hist<<<dim3(20, Bn), 256>>>(1);
    k_select<<<Bn, 256>>>(1, 4096);
    k_hist<<<dim3(20, Bn), 256>>>(2);
    k_select<<<Bn, 256>>>(2, 4096);
    k_hist<<<dim3(20, Bn), 256>>>(3);
    k_select<<<Bn, 256>>>(3, 256);
    k_negsum<<<dim3(20, Bn), 256>>>();
    k_kern<<<dim3(20, Bn*NKER), 256>>>(pred, gtk, tm);
    k_emb1<<<dim3(40, Bn), 256>>>(pred, inst, tm);
    k_means<<<1, 128>>>();
    k_emb2<<<dim3(40, Bn), 256>>>(pred, inst, tm);
    k_final<<<1, 32>>>(out);
}

// round 2
// speedup vs baseline: 2.5276x; 2.5276x over previous
#include <cuda_runtime.h>
#include <math.h>

#define Bn 8
#define Hh 640
#define Ww 640
#define HW (Hh*Ww)          // 409600
#define HW4 (HW/4)
#define NCH 10
#define NKER 5
#define NL 16
#define NEGINF (-1e30f)

// ---------------- scratch ----------------
__device__ unsigned g_negbits[Bn*HW];
__device__ int      g_negcount[Bn];
__device__ int      g_npos[Bn];
__device__ float    g_posSum[Bn], g_posSum2[Bn];
__device__ unsigned g_hist[Bn][4096];
__device__ unsigned g_prefix[Bn];
__device__ int      g_kRem[Bn];
__device__ float    g_negselSum[Bn];
__device__ float    g_kInter[Bn*NKER], g_kU1[Bn*NKER], g_kU2[Bn*NKER];
__device__ float    g_embCnt[Bn][NL];
__device__ float    g_embSum[Bn][NL][4];
__device__ float    g_embCv[Bn][NL];
__device__ float    g_mean[Bn][NL][4];

__device__ __forceinline__ float sigm(float x){ return 1.0f/(1.0f+expf(-x)); }

// ---------------- zero ----------------
__global__ void k_zero(){
    int idx = blockIdx.x*blockDim.x + threadIdx.x;
    if (idx < Bn*4096) ((unsigned*)g_hist)[idx] = 0u;
    if (idx < Bn){
        g_negcount[idx]=0; g_npos[idx]=0; g_posSum[idx]=0.f; g_posSum2[idx]=0.f;
        g_negselSum[idx]=0.f; g_prefix[idx]=0u; g_kRem[idx]=0;
    }
    if (idx < Bn*NKER){ g_kInter[idx]=0.f; g_kU1[idx]=0.f; g_kU2[idx]=0.f; }
    if (idx < Bn*NL){ ((float*)g_embCnt)[idx]=0.f; ((float*)g_embCv)[idx]=0.f; }
    if (idx < Bn*NL*4) ((float*)g_embSum)[idx]=0.f;
}

// ---------------- fused dilate (sigmoid-of-max) + OHEM stats + compaction ---
// grid (20,20,Bn), block (32,8). Tile 32x32, halo 4.
__global__ void k_dilstats(const float* __restrict__ pred,
                           const float* __restrict__ gt,
                           const float* __restrict__ tm){
    __shared__ float sIn[40][41];
    __shared__ float sHm[40][33];
    int b = blockIdx.z;
    int gx0 = blockIdx.x*32 - 4, gy0 = blockIdx.y*32 - 4;
    int tid = threadIdx.y*32 + threadIdx.x;
    int lane = tid & 31;
    const float* p0 = pred + b*NCH*HW;

    for (int idx = tid; idx < 1600; idx += 256){
        int r = idx/40, c = idx - 40*r;
        int gy = gy0 + r, gx = gx0 + c;
        float v = NEGINF;
        if (gy>=0 && gy<Hh && gx>=0 && gx<Ww) v = p0[gy*Ww + gx];
        sIn[r][c] = v;
    }
    __syncthreads();
    for (int idx = tid; idx < 40*32; idx += 256){
        int r = idx >> 5, c = idx & 31;
        float m = sIn[r][c];
        #pragma unroll
        for (int j=1;j<9;j++) m = fmaxf(m, sIn[r][c+j]);
        sHm[r][c] = m;
    }
    __syncthreads();

    int pc = 0; float ps = 0.f, ps2 = 0.f;
    #pragma unroll
    for (int k=0;k<4;k++){
        int r = threadIdx.y*4 + k;          // 0..31
        int c = threadIdx.x;
        float m = sHm[r][c];
        #pragma unroll
        for (int j=1;j<9;j++) m = fmaxf(m, sHm[r+j][c]);
        float v = sigm(m);                  // sigmoid after max (monotone)
        int gy = gy0 + 4 + r, gx = gx0 + 4 + c;
        int gi = b*HW + gy*Ww + gx;
        float g  = gt[gi];
        float mm = tm[gi];
        bool isPos = (g > 0.5f) && (mm > 0.5f);
        bool isNeg = (g <= 0.5f) && (mm > 0.5f);
        if (isPos){ pc++; ps += v; ps2 += v*v; }
        unsigned ball = __ballot_sync(0xffffffffu, isNeg);
        if (isNeg){
            int rank = __popc(ball & ((1u<<lane)-1u));
            int leader = __ffs(ball)-1;
            int base = 0;
            if (lane == leader) base = atomicAdd(&g_negcount[b], __popc(ball));
            base = __shfl_sync(ball, base, leader);
            g_negbits[b*HW + base + rank] = __float_as_uint(v);
        }
    }
    // warp reduce + leader atomics
    #pragma unroll
    for (int o=16;o;o>>=1){
        pc  += __shfl_down_sync(0xffffffffu, pc, o);
        ps  += __shfl_down_sync(0xffffffffu, ps, o);
        ps2 += __shfl_down_sync(0xffffffffu, ps2, o);
    }
    if (lane == 0){
        atomicAdd(&g_npos[b], pc);
        atomicAdd(&g_posSum[b], ps);
        atomicAdd(&g_posSum2[b], ps2);
    }
}

// ---------------- radix-select histograms (match-aggregated) ---------------
__global__ void k_hist(int level){
    __shared__ unsigned h[4096];
    int b = blockIdx.y;
    for (int t = threadIdx.x; t < 4096; t += 256) h[t] = 0u;
    __syncthreads();
    int cnt = g_negcount[b];
    unsigned prefix = g_prefix[b];
    int stride = gridDim.x*blockDim.x;
    const unsigned* nb = g_negbits + b*HW;
    for (int j = blockIdx.x*blockDim.x + threadIdx.x;
         j - (int)threadIdx.x < cnt; j += stride){
        unsigned bin = 0xFFFFFFFFu;
        if (j < cnt){
            unsigned bits = nb[j];
            if (level == 1) bin = bits >> 20;
            else if (level == 2){
                if ((bits>>20) == (prefix>>20)) bin = (bits>>8) & 0xFFFu;
            } else {
                if ((bits>>8) == (prefix>>8)) bin = bits & 0xFFu;
            }
        }
        unsigned grp = __match_any_sync(0xffffffffu, bin);
        int leader = __ffs(grp) - 1;
        if ((int)(threadIdx.x & 31) == leader && bin != 0xFFFFFFFFu)
            atomicAdd(&h[bin], (unsigned)__popc(grp));
    }
    __syncthreads();
    for (int t = threadIdx.x; t < 4096; t += 256)
        if (h[t]) atomicAdd(&g_hist[b][t], h[t]);
}

// select bin (parallel suffix scan), update prefix/kRem, clear hist. grid Bn x 256
__global__ void k_select(int level, int nbins){
    __shared__ unsigned part[256];
    __shared__ unsigned orig[256];
    int b = blockIdx.x;
    int t = threadIdx.x;
    int k;
    if (level == 1){
        k = 3*g_npos[b];
        int nt = g_negcount[b];
        if (k > nt) k = nt;
    } else k = g_kRem[b];

    if (k <= 0){
        if (t == 0){ g_kRem[b] = 0; g_prefix[b] = 0xFFFFFFFFu; }
    } else {
        int per = nbins >> 8;                   // 16 or 1
        int hi = nbins - 1 - t*per;             // descending chunks
        unsigned s = 0;
        for (int i=0;i<per;i++) s += g_hist[b][hi-i];
        part[t] = s; orig[t] = s;
        __syncthreads();
        for (int off=1; off<256; off<<=1){
            unsigned v = (t >= off) ? part[t-off] : 0u;
            __syncthreads();
            part[t] += v;
            __syncthreads();
        }
        unsigned incl = part[t];
        unsigned excl = incl - orig[t];
        if ((long long)excl < (long long)k && (long long)k <= (long long)incl){
            long long acc = excl;
            int chosen = hi;
            for (int i=0;i<per;i++){
                unsigned c = g_hist[b][hi-i];
                if (acc + (long long)c >= (long long)k){ chosen = hi-i; break; }
                acc += c;
            }
            g_kRem[b] = k - (int)acc;
            unsigned ch = (unsigned)chosen;
            if (level == 1)      g_prefix[b] = ch << 20;
            else if (level == 2) g_prefix[b] |= ch << 8;
            else                 g_prefix[b] |= ch;
        }
        __syncthreads();
    }
    __syncthreads();
    for (int i=t; i<4096; i+=256) g_hist[b][i] = 0u;
}

// sum v^2 over negatives strictly above threshold  grid (32,Bn) x 256
__global__ void k_negsum(){
    int b = blockIdx.y;
    unsigned T = g_prefix[b];
    int cnt = g_negcount[b];
    int stride = gridDim.x*blockDim.x;
    const unsigned* nb = g_negbits + b*HW;
    float s = 0.f;
    for (int j = blockIdx.x*blockDim.x + threadIdx.x; j < cnt; j += stride){
        unsigned bits = nb[j];
        if (bits > T){ float v = __uint_as_float(bits); s += v*v; }
    }
    #pragma unroll
    for (int o=16;o;o>>=1) s += __shfl_down_sync(0xffffffffu, s, o);
    if ((threadIdx.x & 31) == 0 && s != 0.f) atomicAdd(&g_negselSum[b], s);
}

// ---------------- kernels dice: all 5 channels per batch, float4 -----------
// grid (64, Bn) x 256
__global__ void k_kern(const float* __restrict__ pred,
                       const float* __restrict__ gtk,
                       const float* __restrict__ tm){
    int b = blockIdx.y;
    const float4* mm4 = (const float4*)(tm + b*HW);
    float si[5], s1[5], s2[5];
    #pragma unroll
    for (int kc=0;kc<5;kc++){ si[kc]=0.f; s1[kc]=0.f; s2[kc]=0.f; }
    int stride = gridDim.x*blockDim.x;
    for (int i = blockIdx.x*blockDim.x + threadIdx.x; i < HW4; i += stride){
        float4 m = mm4[i];
        #pragma unroll
        for (int kc=0;kc<5;kc++){
            float4 p = ((const float4*)(pred + (b*NCH + 1 + kc)*HW))[i];
            float4 g = ((const float4*)(gtk  + (b*NKER + kc)*HW))[i];
            if (m.x > 0.5f){ float pp = sigm(p.x); si[kc]+=pp*g.x; s1[kc]+=pp*pp; s2[kc]+=g.x; }
            if (m.y > 0.5f){ float pp = sigm(p.y); si[kc]+=pp*g.y; s1[kc]+=pp*pp; s2[kc]+=g.y; }
            if (m.z > 0.5f){ float pp = sigm(p.z); si[kc]+=pp*g.z; s1[kc]+=pp*pp; s2[kc]+=g.z; }
            if (m.w > 0.5f){ float pp = sigm(p.w); si[kc]+=pp*g.w; s1[kc]+=pp*pp; s2[kc]+=g.w; }
        }
    }
    int lane = threadIdx.x & 31;
    #pragma unroll
    for (int kc=0;kc<5;kc++){
        float a = si[kc], u = s1[kc], c = s2[kc];
        #pragma unroll
        for (int o=16;o;o>>=1){
            a += __shfl_down_sync(0xffffffffu, a, o);
            u += __shfl_down_sync(0xffffffffu, u, o);
            c += __shfl_down_sync(0xffffffffu, c, o);
        }
        if (lane == 0){
            atomicAdd(&g_kInter[b*NKER+kc], a);
            atomicAdd(&g_kU1[b*NKER+kc], u);
            atomicAdd(&g_kU2[b*NKER+kc], c);
        }
    }
}

// ---------------- emb pass 1: per-label counts + sums ----------------------
// grid (64, Bn) x 256, per-warp smem tables
__global__ void k_emb1(const float* __restrict__ pred,
                       const int* __restrict__ inst,
                       const float* __restrict__ tm){
    __shared__ float sA[8][NL][5];
    int b = blockIdx.y;
    int w = threadIdx.x >> 5;
    for (int i = threadIdx.x; i < 8*NL*5; i += 256) ((float*)sA)[i] = 0.f;
    __syncthreads();
    const float4* tm4 = (const float4*)(tm + b*HW);
    const int4*   in4 = (const int4*)(inst + b*HW);
    const float4* e0 = (const float4*)(pred + (b*NCH + 6)*HW);
    const float4* e1 = (const float4*)(pred + (b*NCH + 7)*HW);
    const float4* e2 = (const float4*)(pred + (b*NCH + 8)*HW);
    const float4* e3 = (const float4*)(pred + (b*NCH + 9)*HW);
    int stride = gridDim.x*blockDim.x;
    for (int i = blockIdx.x*blockDim.x + threadIdx.x; i < HW4; i += stride){
        float4 m = tm4[i]; int4 gi = in4[i];
        float4 a = e0[i], bb = e1[i], c = e2[i], d = e3[i];
        if (m.x > 0.5f){ float* p = sA[w][gi.x & 15];
            atomicAdd(p,1.f); atomicAdd(p+1,a.x); atomicAdd(p+2,bb.x); atomicAdd(p+3,c.x); atomicAdd(p+4,d.x); }
        if (m.y > 0.5f){ float* p = sA[w][gi.y & 15];
            atomicAdd(p,1.f); atomicAdd(p+1,a.y); atomicAdd(p+2,bb.y); atomicAdd(p+3,c.y); atomicAdd(p+4,d.y); }
        if (m.z > 0.5f){ float* p = sA[w][gi.z & 15];
            atomicAdd(p,1.f); atomicAdd(p+1,a.z); atomicAdd(p+2,bb.z); atomicAdd(p+3,c.z); atomicAdd(p+4,d.z); }
        if (m.w > 0.5f){ float* p = sA[w][gi.w & 15];
            atomicAdd(p,1.f); atomicAdd(p+1,a.w); atomicAdd(p+2,bb.w); atomicAdd(p+3,c.w); atomicAdd(p+4,d.w); }
    }
    __syncthreads();
    for (int i = threadIdx.x; i < NL*5; i += 256){
        int l = i/5, comp = i - 5*l;
        float s = 0.f;
        #pragma unroll
        for (int ww=0; ww<8; ww++) s += sA[ww][l][comp];
        if (s != 0.f){
            if (comp == 0) atomicAdd(&g_embCnt[b][l], s);
            else           atomicAdd(&g_embSum[b][l][comp-1], s);
        }
    }
}

__global__ void k_means(){
    int t = blockIdx.x*blockDim.x + threadIdx.x;
    if (t >= Bn*NL) return;
    int b = t / NL, l = t - b*NL;
    float inv = 1.f / fmaxf(g_embCnt[b][l], 1.f);
    #pragma unroll
    for (int d=0;d<4;d++) g_mean[b][l][d] = g_embSum[b][l][d]*inv;
}

// ---------------- emb pass 2: hinge variance -------------------------------
__global__ void k_emb2(const float* __restrict__ pred,
                       const int* __restrict__ inst,
                       const float* __restrict__ tm){
    __shared__ float sCv[8][NL];
    __shared__ float sM[NL][4];
    int b = blockIdx.y;
    int w = threadIdx.x >> 5;
    for (int i = threadIdx.x; i < 8*NL; i += 256) ((float*)sCv)[i] = 0.f;
    if (threadIdx.x < NL*4)
        ((float*)sM)[threadIdx.x] = ((float*)g_mean[b])[threadIdx.x];
    __syncthreads();
    const float4* tm4 = (const float4*)(tm + b*HW);
    const int4*   in4 = (const int4*)(inst + b*HW);
    const float4* e0 = (const float4*)(pred + (b*NCH + 6)*HW);
    const float4* e1 = (const float4*)(pred + (b*NCH + 7)*HW);
    const float4* e2 = (const float4*)(pred + (b*NCH + 8)*HW);
    const float4* e3 = (const float4*)(pred + (b*NCH + 9)*HW);
    int stride = gridDim.x*blockDim.x;
    for (int i = blockIdx.x*blockDim.x + threadIdx.x; i < HW4; i += stride){
        float4 m = tm4[i]; int4 gi = in4[i];
        float4 a = e0[i], bb = e1[i], c = e2[i], d = e3[i];
        #pragma unroll
        for (int comp=0; comp<4; comp++){
            float mv = comp==0?m.x:comp==1?m.y:comp==2?m.z:m.w;
            if (mv > 0.5f){
                int l = ((comp==0?gi.x:comp==1?gi.y:comp==2?gi.z:gi.w) & 15);
                float v0 = (comp==0?a.x:comp==1?a.y:comp==2?a.z:a.w) - sM[l][0];
                float v1 = (comp==0?bb.x:comp==1?bb.y:comp==2?bb.z:bb.w) - sM[l][1];
                float v2 = (comp==0?c.x:comp==1?c.y:comp==2?c.z:c.w) - sM[l][2];
                float v3 = (comp==0?d.x:comp==1?d.y:comp==2?d.z:d.w) - sM[l][3];
                float dd = sqrtf(v0*v0+v1*v1+v2*v2+v3*v3 + 1e-12f);
                float h = dd - 0.5f;
                if (h > 0.f) atomicAdd(&sCv[w][l], h*h);
            }
        }
    }
    __syncthreads();
    for (int i = threadIdx.x; i < NL; i += 256){
        float s = 0.f;
        #pragma unroll
        for (int ww=0; ww<8; ww++) s += sCv[ww][i];
        if (s != 0.f) atomicAdd(&g_embCv[b][i], s);
    }
}

// ---------------- final assembly -------------------------------------------
__global__ void k_final(float* out){
    if (threadIdx.x != 0 || blockIdx.x != 0) return;
    float loss_text = 0.f;
    for (int b=0;b<Bn;b++){
        float inter = g_posSum[b];
        float uni = g_posSum2[b] + g_negselSum[b] + (float)g_npos[b] + 1e-6f;
        if (g_kRem[b] > 0){
            float tv = __uint_as_float(g_prefix[b]);
            uni += (float)g_kRem[b]*tv*tv;
        }
        loss_text += 1.f - 2.f*inter/uni;
    }
    loss_text /= (float)Bn;
    float loss_k = 0.f;
    for (int r=0;r<Bn*NKER;r++){
        float uni = g_kU1[r] + g_kU2[r] + 1e-6f;
        loss_k += 1.f - 2.f*g_kInter[r]/uni;
    }
    loss_k /= (float)(Bn*NKER);
    float lvT=0.f, ldT=0.f, lrT=0.f;
    for (int b=0;b<Bn;b++){
        int n=0;
        bool pres[NL];
        for (int l=0;l<NL;l++){ pres[l] = g_embCnt[b][l] > 0.f; if (pres[l]) n++; }
        float nf = (float)n;
        float lv = 0.f;
        for (int l=0;l<NL;l++)
            if (pres[l]) lv += g_embCv[b][l] / fmaxf(g_embCnt[b][l], 1.f);
        lv /= fmaxf(nf, 1.f);
        float ld = 0.f;
        for (int i=0;i<NL;i++) for (int j=i+1;j<NL;j++){
            if (pres[i] && pres[j]){
                float d2=0.f;
                for (int d=0;d<4;d++){
                    float df = g_mean[b][i][d]-g_mean[b][j][d];
                    d2 += df*df;
                }
                float pd = sqrtf(d2 + 1e-12f);
                float h = fmaxf(3.0f - pd, 0.f);
                ld += h*h;
            }
        }
        ld /= fmaxf(nf*(nf-1.f), 1.f);
        float lr = 0.f;
        for (int l=0;l<NL;l++){
            if (pres[l]){
                float d2=0.f;
                for (int d=0;d<4;d++) d2 += g_mean[b][l][d]*g_mean[b][l][d];
                lr += sqrtf(d2 + 1e-12f);
            }
        }
        lr /= fmaxf(nf, 1.f);
        float act = (n > 1) ? 1.f : 0.f;
        lvT += act*lv; ldT += act*ld; lrT += act*lr;
    }
    float loss_emb = 0.25f*(lvT + ldT + 0.001f*(lrT/(float)Bn));
    float loss = loss_k + 0.5f*loss_text + loss_emb;
    out[0]=loss; out[1]=loss_text; out[2]=loss_k; out[3]=loss_emb;
}

// ---------------- launch ---------------------------------------------------
extern "C" void kernel_launch(void* const* d_in, const int* in_sizes, int n_in,
                              void* d_out, int out_size){
    const float* pred   = (const float*)d_in[0];
    const float* gtText = (const float*)d_in[1];
    const float* gtk    = (const float*)d_in[2];
    const float* tm     = (const float*)d_in[3];
    const int*   inst   = (const int*)d_in[4];
    float* out = (float*)d_out;

    k_zero<<<(Bn*4096+255)/256, 256>>>();
    k_dilstats<<<dim3(20,20,Bn), dim3(32,8)>>>(pred, gtText, tm);
    k_hist<<<dim3(32, Bn), 256>>>(1);
    k_select<<<Bn, 256>>>(1, 4096);
    k_hist<<<dim3(32, Bn), 256>>>(2);
    k_select<<<Bn, 256>>>(2, 4096);
    k_hist<<<dim3(32, Bn), 256>>>(3);
    k_select<<<Bn, 256>>>(3, 256);
    k_negsum<<<dim3(32, Bn), 256>>>();
    k_kern<<<dim3(64, Bn), 256>>>(pred, gtk, tm);
    k_emb1<<<dim3(64, Bn), 256>>>(pred, inst, tm);
    k_means<<<1, 128>>>();
    k_emb2<<<dim3(64, Bn), 256>>>(pred, inst, tm);
    k_final<<<1, 32>>>(out);
}